// round 15
// baseline (speedup 1.0000x reference)
#include <cuda_runtime.h>

#define BATCH   16
#define NPTS    4096
#define NB      128
#define THREADS 256
#define PPT     4
#define QPB     (THREADS * PPT)      // 1024 queries per phase1 block
#define GRIDX   (NPTS / QPB)         // 4 -> phase1 grid (4,16,2) = 128 blocks
#define TILECAP 1024                 // smem candidate tile (16KB)
#define MARGIN  3                    // phase-1 window margin (buckets)
#define CSPLIT  8                    // phase-2 candidate splits
#define CSEG    (NPTS / CSPLIT)      // 512
#define XMIN_F  (-6.0f)
#define XMAX_F  (6.0f)
#define WBUCK   ((XMAX_F - XMIN_F) / (float)NB)
#define BSCALE  ((float)NB / (XMAX_F - XMIN_F))

__device__ double       g_acc[2];
__device__ float4       g_pts[2 * BATCH * NPTS];     // binned (x,y,z,||p||^2)
__device__ int          g_off[2 * BATCH * (NB + 1)];
__device__ int          g_fcnt[2 * BATCH];           // flagged count per pair
__device__ int          g_fidx[2 * BATCH * NPTS];    // flagged query indices
__device__ unsigned int g_fmin[2 * BATCH * NPTS];    // flagged partial mins (enc)
__device__ unsigned int g_pdone[2 * BATCH];          // per-pair phase2 tickets
__device__ unsigned int g_done;                      // global fold ticket

__device__ __forceinline__ unsigned int enc_f(float f) {
    unsigned int u = __float_as_uint(f);
    return (u & 0x80000000u) ? ~u : (u | 0x80000000u);
}
__device__ __forceinline__ float dec_f(unsigned int k) {
    unsigned int u = (k & 0x80000000u) ? (k & 0x7FFFFFFFu) : ~k;
    return __uint_as_float(u);
}

// One block per (batch, set): histogram -> parallel prefix -> scatter.
__global__ __launch_bounds__(1024) void bin_kernel(
    const float* __restrict__ xyz1, const float* __restrict__ xyz2)
{
    const int b = blockIdx.x, set = blockIdx.y;
    if (b == 0 && set == 0) {
        if (threadIdx.x < 2)  g_acc[threadIdx.x] = 0.0;
        if (threadIdx.x < 2 * BATCH) { g_fcnt[threadIdx.x] = 0; g_pdone[threadIdx.x] = 0u; }
        if (threadIdx.x == 0) g_done = 0u;
    }

    const float* __restrict__ src = ((set == 0) ? xyz1 : xyz2) + (size_t)b * NPTS * 3;
    __shared__ int cnt[NB];
    __shared__ int cur[NB + 1];
    __shared__ int wsum[NB / 32];
    const int tid = threadIdx.x;

    for (int k = tid; k < NB; k += 1024) cnt[k] = 0;
    __syncthreads();
    for (int i = tid; i < NPTS; i += 1024) {
        float x = src[3 * i];
        int bk = min(max((int)((x - XMIN_F) * BSCALE), 0), NB - 1);
        atomicAdd(&cnt[bk], 1);
    }
    __syncthreads();
    int v = 0, s = 0;
    if (tid < NB) {
        v = cnt[tid]; s = v;
#pragma unroll
        for (int o = 1; o < 32; o <<= 1) {
            int n = __shfl_up_sync(0xffffffffu, s, o);
            if ((tid & 31) >= o) s += n;
        }
        if ((tid & 31) == 31) wsum[tid >> 5] = s;
    }
    __syncthreads();
    if (tid < NB) {
        int add = 0;
#pragma unroll
        for (int k = 0; k < NB / 32; k++) if (k < (tid >> 5)) add += wsum[k];
        cur[tid] = s - v + add;
        if (tid == NB - 1) cur[NB] = s + add;
    }
    __syncthreads();
    int* off = g_off + (set * BATCH + b) * (NB + 1);
    for (int k = tid; k <= NB; k += 1024) off[k] = cur[k];
    float4* dst = g_pts + (set * BATCH + b) * NPTS;
    for (int i = tid; i < NPTS; i += 1024) {
        float x = src[3 * i], y = src[3 * i + 1], z = src[3 * i + 2];
        int bk = min(max((int)((x - XMIN_F) * BSCALE), 0), NB - 1);
        int pos = atomicAdd(&cur[bk], 1);
        dst[pos] = make_float4(x, y, z, x * x + y * y + z * z);
    }
}

// Phase 1: fixed block-window dense scan + per-query certification (PPT=4).
__global__ __launch_bounds__(THREADS) void phase1_kernel()
{
    const int dir  = blockIdx.z;
    const int b    = blockIdx.y;
    const int pair = dir * BATCH + b;
    const int tid  = threadIdx.x;
    const int lane = tid & 31;

    __shared__ float4 tile[TILECAP];
    __shared__ int    soff[NB + 1];
    __shared__ int    sj[2];
    __shared__ float  red[THREADS / 32];

    const float4* __restrict__ qp = g_pts + (dir * BATCH + b) * NPTS;
    const float4* __restrict__ cp = g_pts + ((1 - dir) * BATCH + b) * NPTS;
    const int*    __restrict__ go = g_off + ((1 - dir) * BATCH + b) * (NB + 1);

    for (int k = tid; k <= NB; k += THREADS) soff[k] = go[k];

    const int q0 = blockIdx.x * QPB;
    float rx[PPT], qx[PPT], qy[PPT], qz[PPT], qs[PPT], mn[PPT];
#pragma unroll
    for (int p = 0; p < PPT; p++) {
        float4 v = qp[q0 + tid + p * THREADS];
        rx[p] = v.x;
        qx[p] = -2.0f * v.x; qy[p] = -2.0f * v.y; qz[p] = -2.0f * v.z;
        qs[p] = v.w;
        mn[p] = 3.4e38f;
    }
    if (tid == 0)
        sj[0] = min(max((int)((qp[q0].x - XMIN_F) * BSCALE), 0), NB - 1);
    if (tid == THREADS - 1)
        sj[1] = min(max((int)((qp[q0 + QPB - 1].x - XMIN_F) * BSCALE), 0), NB - 1);
    __syncthreads();
    const int wl = max(sj[0] - MARGIN, 0);
    const int wh = min(sj[1] + MARGIN, NB - 1);
    const int m0 = soff[wl], m1 = soff[wh + 1];

    // Dense smem scan over the window.
    for (int base = m0; base < m1; base += TILECAP) {
        int cnt = min(TILECAP, m1 - base);
        __syncthreads();
        for (int i = tid; i < cnt; i += THREADS) tile[i] = cp[base + i];
        __syncthreads();
#pragma unroll 4
        for (int i = 0; i < cnt; i++) {
            float4 cv = tile[i];
#pragma unroll
            for (int p = 0; p < PPT; p++) {
                float t = fmaf(qx[p], cv.x,
                          fmaf(qy[p], cv.y,
                          fmaf(qz[p], cv.z, cv.w)));
                mn[p] = fminf(mn[p], t);
            }
        }
    }

    // Per-query certification; certified sum here, rest compacted.
    const float el = XMIN_F + wl * WBUCK;
    const float er = XMIN_F + (wh + 1) * WBUCK;
    float s = 0.0f;
#pragma unroll
    for (int p = 0; p < PPT; p++) {
        float d = mn[p] + qs[p];
        bool cl = (wl == 0)      || ((rx[p] - el) * (rx[p] - el) >= d);
        bool cr = (wh == NB - 1) || ((er - rx[p]) * (er - rx[p]) >= d);
        bool cert = cl && cr;
        if (cert) s += d;
        unsigned bal = __ballot_sync(0xffffffffu, !cert);
        if (bal) {
            int leader = __ffs(bal) - 1;
            unsigned basepos = 0;
            if (lane == leader)
                basepos = (unsigned)atomicAdd(&g_fcnt[pair], __popc(bal));
            basepos = __shfl_sync(0xffffffffu, basepos, leader);
            if (!cert) {
                int rank = __popc(bal & ((1u << lane) - 1u));
                int slot = pair * NPTS + (int)basepos + rank;
                g_fidx[slot] = q0 + tid + p * THREADS;
                g_fmin[slot] = 0xFFFFFFFFu;
            }
        }
    }

#pragma unroll
    for (int o = 16; o > 0; o >>= 1) s += __shfl_down_sync(0xffffffffu, s, o);
    if (lane == 0) red[tid >> 5] = s;
    __syncthreads();
    if (tid < THREADS / 32) {
        s = red[tid];
#pragma unroll
        for (int o = (THREADS / 64); o > 0; o >>= 1)
            s += __shfl_down_sync(0xffu, s, o);
        if (tid == 0) atomicAdd(&g_acc[dir], (double)s);
    }
}

// Phase 2: brute-force flagged queries over candidate segments; the last
// block per pair folds that pair; the last folded pair writes the output.
__global__ __launch_bounds__(THREADS) void phase2_kernel(float* out)
{
    const int pair = blockIdx.y;
    const int dir  = pair >> 4;
    const int b    = pair & (BATCH - 1);
    const int tid  = threadIdx.x;
    const int nf   = g_fcnt[pair];

    __shared__ float4       tile[CSEG];
    __shared__ float        red[THREADS / 32];
    __shared__ unsigned int sticket;
    const float4* __restrict__ qp = g_pts + (dir * BATCH + b) * NPTS;
    const float4* __restrict__ cp = g_pts + ((1 - dir) * BATCH + b) * NPTS;

    if (nf > 0) {
        const int seg = blockIdx.x * CSEG;
        for (int i = tid; i < CSEG; i += THREADS) tile[i] = cp[seg + i];
        __syncthreads();

        for (int f = tid; f < nf; f += THREADS) {
            int n = g_fidx[pair * NPTS + f];
            float4 qv = qp[n];
            float qx = -2.0f * qv.x, qy = -2.0f * qv.y, qz = -2.0f * qv.z;
            float m0 = 3.4e38f, m1 = 3.4e38f, m2 = 3.4e38f, m3 = 3.4e38f;
#pragma unroll 4
            for (int i = 0; i < CSEG; i += 4) {
                float4 c0 = tile[i],     c1 = tile[i + 1];
                float4 c2 = tile[i + 2], c3 = tile[i + 3];
                m0 = fminf(m0, fmaf(qx, c0.x, fmaf(qy, c0.y, fmaf(qz, c0.z, c0.w))));
                m1 = fminf(m1, fmaf(qx, c1.x, fmaf(qy, c1.y, fmaf(qz, c1.z, c1.w))));
                m2 = fminf(m2, fmaf(qx, c2.x, fmaf(qy, c2.y, fmaf(qz, c2.z, c2.w))));
                m3 = fminf(m3, fmaf(qx, c3.x, fmaf(qy, c3.y, fmaf(qz, c3.z, c3.w))));
            }
            float mn = fminf(fminf(m0, m1), fminf(m2, m3));
            atomicMin(&g_fmin[pair * NPTS + f], enc_f(mn));
        }
    }

    // Per-pair ticket (all CSPLIT blocks participate, even if nf==0).
    __syncthreads();
    if (tid == 0) {
        __threadfence();
        sticket = atomicAdd(&g_pdone[pair], 1u);
    }
    __syncthreads();
    if (sticket != CSPLIT - 1) return;

    // Last block of this pair: fold its flagged mins.
    float s = 0.0f;
    for (int f = tid; f < nf; f += THREADS)
        s += dec_f(g_fmin[pair * NPTS + f]) + qp[g_fidx[pair * NPTS + f]].w;
#pragma unroll
    for (int o = 16; o > 0; o >>= 1) s += __shfl_down_sync(0xffffffffu, s, o);
    if ((tid & 31) == 0) red[tid >> 5] = s;
    __syncthreads();
    if (tid < THREADS / 32) {
        s = red[tid];
#pragma unroll
        for (int o = (THREADS / 64); o > 0; o >>= 1)
            s += __shfl_down_sync(0xffu, s, o);
    }
    if (tid == 0) {
        if (s != 0.0f) atomicAdd(&g_acc[dir], (double)s);
        __threadfence();
        sticket = atomicAdd(&g_done, 1u);
    }
    __syncthreads();
    if (sticket == 2 * BATCH - 1 && tid < 2) {
        // Final pair folded: all g_acc contributions visible.
        out[tid] = (float)(g_acc[tid] / (double)(BATCH * NPTS));
    }
}

extern "C" void kernel_launch(void* const* d_in, const int* in_sizes, int n_in,
                              void* d_out, int out_size)
{
    const float* xyz1 = (const float*)d_in[0];
    const float* xyz2 = (const float*)d_in[1];
    float* out = (float*)d_out;

    bin_kernel<<<dim3(BATCH, 2), 1024>>>(xyz1, xyz2);
    phase1_kernel<<<dim3(GRIDX, BATCH, 2), THREADS>>>();        // 128 blocks
    phase2_kernel<<<dim3(CSPLIT, 2 * BATCH), THREADS>>>(out);   // 256 blocks
}

// round 16
// speedup vs baseline: 1.3065x; 1.3065x over previous
#include <cuda_runtime.h>

#define BATCH   16
#define NPTS    4096
#define NB      128
#define THREADS 256
#define PPT     2
#define QPB     (THREADS * PPT)      // 512 queries per phase1 block
#define GRIDX   (NPTS / QPB)         // 8 -> phase1 grid (8,16,2) = 256 blocks
#define TILECAP 1024                 // smem candidate tile (16KB)
#define MARGIN  3                    // phase-1 window margin (buckets)
#define CSPLIT  8                    // phase-2 candidate splits
#define CSEG    (NPTS / CSPLIT)      // 512
#define XMIN_F  (-6.0f)
#define XMAX_F  (6.0f)
#define WBUCK   ((XMAX_F - XMIN_F) / (float)NB)
#define BSCALE  ((float)NB / (XMAX_F - XMIN_F))

__device__ double       g_acc[2];
__device__ float4       g_pts[2 * BATCH * NPTS];     // binned (x,y,z,||p||^2)
__device__ int          g_off[2 * BATCH * (NB + 1)];
__device__ int          g_fcnt[2 * BATCH];           // flagged count per pair
__device__ int          g_fidx[2 * BATCH * NPTS];    // flagged query indices
__device__ unsigned int g_fmin[2 * BATCH * NPTS];    // flagged partial mins (enc)
__device__ unsigned int g_pdone[2 * BATCH];          // per-pair phase2 tickets
__device__ unsigned int g_done;                      // global fold ticket

__device__ __forceinline__ unsigned int enc_f(float f) {
    unsigned int u = __float_as_uint(f);
    return (u & 0x80000000u) ? ~u : (u | 0x80000000u);
}
__device__ __forceinline__ float dec_f(unsigned int k) {
    unsigned int u = (k & 0x80000000u) ? (k & 0x7FFFFFFFu) : ~k;
    return __uint_as_float(u);
}

// One block per (batch, set): histogram -> parallel prefix -> scatter.
__global__ __launch_bounds__(1024) void bin_kernel(
    const float* __restrict__ xyz1, const float* __restrict__ xyz2)
{
    const int b = blockIdx.x, set = blockIdx.y;
    if (b == 0 && set == 0) {
        if (threadIdx.x < 2)  g_acc[threadIdx.x] = 0.0;
        if (threadIdx.x < 2 * BATCH) { g_fcnt[threadIdx.x] = 0; g_pdone[threadIdx.x] = 0u; }
        if (threadIdx.x == 0) g_done = 0u;
    }

    const float* __restrict__ src = ((set == 0) ? xyz1 : xyz2) + (size_t)b * NPTS * 3;
    __shared__ int cnt[NB];
    __shared__ int cur[NB + 1];
    __shared__ int wsum[NB / 32];
    const int tid = threadIdx.x;

    for (int k = tid; k < NB; k += 1024) cnt[k] = 0;
    __syncthreads();
    for (int i = tid; i < NPTS; i += 1024) {
        float x = src[3 * i];
        int bk = min(max((int)((x - XMIN_F) * BSCALE), 0), NB - 1);
        atomicAdd(&cnt[bk], 1);
    }
    __syncthreads();
    int v = 0, s = 0;
    if (tid < NB) {
        v = cnt[tid]; s = v;
#pragma unroll
        for (int o = 1; o < 32; o <<= 1) {
            int n = __shfl_up_sync(0xffffffffu, s, o);
            if ((tid & 31) >= o) s += n;
        }
        if ((tid & 31) == 31) wsum[tid >> 5] = s;
    }
    __syncthreads();
    if (tid < NB) {
        int add = 0;
#pragma unroll
        for (int k = 0; k < NB / 32; k++) if (k < (tid >> 5)) add += wsum[k];
        cur[tid] = s - v + add;
        if (tid == NB - 1) cur[NB] = s + add;
    }
    __syncthreads();
    int* off = g_off + (set * BATCH + b) * (NB + 1);
    for (int k = tid; k <= NB; k += 1024) off[k] = cur[k];
    float4* dst = g_pts + (set * BATCH + b) * NPTS;
    for (int i = tid; i < NPTS; i += 1024) {
        float x = src[3 * i], y = src[3 * i + 1], z = src[3 * i + 2];
        int bk = min(max((int)((x - XMIN_F) * BSCALE), 0), NB - 1);
        int pos = atomicAdd(&cur[bk], 1);
        dst[pos] = make_float4(x, y, z, x * x + y * y + z * z);
    }
}

// Phase 1: fixed block-window dense scan + per-query certification (PPT=2).
__global__ __launch_bounds__(THREADS) void phase1_kernel()
{
    const int dir  = blockIdx.z;
    const int b    = blockIdx.y;
    const int pair = dir * BATCH + b;
    const int tid  = threadIdx.x;
    const int lane = tid & 31;

    __shared__ float4 tile[TILECAP];
    __shared__ int    soff[NB + 1];
    __shared__ int    sj[2];
    __shared__ float  red[THREADS / 32];

    const float4* __restrict__ qp = g_pts + (dir * BATCH + b) * NPTS;
    const float4* __restrict__ cp = g_pts + ((1 - dir) * BATCH + b) * NPTS;
    const int*    __restrict__ go = g_off + ((1 - dir) * BATCH + b) * (NB + 1);

    for (int k = tid; k <= NB; k += THREADS) soff[k] = go[k];

    const int q0 = blockIdx.x * QPB;
    float rx[PPT], qx[PPT], qy[PPT], qz[PPT], qs[PPT], mn[PPT];
#pragma unroll
    for (int p = 0; p < PPT; p++) {
        float4 v = qp[q0 + tid + p * THREADS];
        rx[p] = v.x;
        qx[p] = -2.0f * v.x; qy[p] = -2.0f * v.y; qz[p] = -2.0f * v.z;
        qs[p] = v.w;
        mn[p] = 3.4e38f;
    }
    if (tid == 0)
        sj[0] = min(max((int)((qp[q0].x - XMIN_F) * BSCALE), 0), NB - 1);
    if (tid == THREADS - 1)
        sj[1] = min(max((int)((qp[q0 + QPB - 1].x - XMIN_F) * BSCALE), 0), NB - 1);
    __syncthreads();
    const int wl = max(sj[0] - MARGIN, 0);
    const int wh = min(sj[1] + MARGIN, NB - 1);
    const int m0 = soff[wl], m1 = soff[wh + 1];

    // Dense smem scan over the window.
    for (int base = m0; base < m1; base += TILECAP) {
        int cnt = min(TILECAP, m1 - base);
        __syncthreads();
        for (int i = tid; i < cnt; i += THREADS) tile[i] = cp[base + i];
        __syncthreads();
#pragma unroll 4
        for (int i = 0; i < cnt; i++) {
            float4 cv = tile[i];
#pragma unroll
            for (int p = 0; p < PPT; p++) {
                float t = fmaf(qx[p], cv.x,
                          fmaf(qy[p], cv.y,
                          fmaf(qz[p], cv.z, cv.w)));
                mn[p] = fminf(mn[p], t);
            }
        }
    }

    // Per-query certification; certified sum here, rest compacted.
    const float el = XMIN_F + wl * WBUCK;
    const float er = XMIN_F + (wh + 1) * WBUCK;
    float s = 0.0f;
#pragma unroll
    for (int p = 0; p < PPT; p++) {
        float d = mn[p] + qs[p];
        bool cl = (wl == 0)      || ((rx[p] - el) * (rx[p] - el) >= d);
        bool cr = (wh == NB - 1) || ((er - rx[p]) * (er - rx[p]) >= d);
        bool cert = cl && cr;
        if (cert) s += d;
        unsigned bal = __ballot_sync(0xffffffffu, !cert);
        if (bal) {
            int leader = __ffs(bal) - 1;
            unsigned basepos = 0;
            if (lane == leader)
                basepos = (unsigned)atomicAdd(&g_fcnt[pair], __popc(bal));
            basepos = __shfl_sync(0xffffffffu, basepos, leader);
            if (!cert) {
                int rank = __popc(bal & ((1u << lane) - 1u));
                int slot = pair * NPTS + (int)basepos + rank;
                g_fidx[slot] = q0 + tid + p * THREADS;
                g_fmin[slot] = 0xFFFFFFFFu;
            }
        }
    }

#pragma unroll
    for (int o = 16; o > 0; o >>= 1) s += __shfl_down_sync(0xffffffffu, s, o);
    if (lane == 0) red[tid >> 5] = s;
    __syncthreads();
    if (tid < THREADS / 32) {
        s = red[tid];
#pragma unroll
        for (int o = (THREADS / 64); o > 0; o >>= 1)
            s += __shfl_down_sync(0xffu, s, o);
        if (tid == 0) atomicAdd(&g_acc[dir], (double)s);
    }
}

// Phase 2: brute-force flagged queries over candidate segments; the last
// block per pair folds that pair; the last folded pair writes the output.
__global__ __launch_bounds__(THREADS) void phase2_kernel(float* out)
{
    const int pair = blockIdx.y;
    const int dir  = pair >> 4;
    const int b    = pair & (BATCH - 1);
    const int tid  = threadIdx.x;
    const int nf   = g_fcnt[pair];

    __shared__ float4       tile[CSEG];
    __shared__ float        red[THREADS / 32];
    __shared__ unsigned int sticket;
    const float4* __restrict__ qp = g_pts + (dir * BATCH + b) * NPTS;
    const float4* __restrict__ cp = g_pts + ((1 - dir) * BATCH + b) * NPTS;

    if (nf > 0) {
        const int seg = blockIdx.x * CSEG;
        for (int i = tid; i < CSEG; i += THREADS) tile[i] = cp[seg + i];
        __syncthreads();

        for (int f = tid; f < nf; f += THREADS) {
            int n = g_fidx[pair * NPTS + f];
            float4 qv = qp[n];
            float qx = -2.0f * qv.x, qy = -2.0f * qv.y, qz = -2.0f * qv.z;
            float m0 = 3.4e38f, m1 = 3.4e38f, m2 = 3.4e38f, m3 = 3.4e38f;
#pragma unroll 4
            for (int i = 0; i < CSEG; i += 4) {
                float4 c0 = tile[i],     c1 = tile[i + 1];
                float4 c2 = tile[i + 2], c3 = tile[i + 3];
                m0 = fminf(m0, fmaf(qx, c0.x, fmaf(qy, c0.y, fmaf(qz, c0.z, c0.w))));
                m1 = fminf(m1, fmaf(qx, c1.x, fmaf(qy, c1.y, fmaf(qz, c1.z, c1.w))));
                m2 = fminf(m2, fmaf(qx, c2.x, fmaf(qy, c2.y, fmaf(qz, c2.z, c2.w))));
                m3 = fminf(m3, fmaf(qx, c3.x, fmaf(qy, c3.y, fmaf(qz, c3.z, c3.w))));
            }
            float mn = fminf(fminf(m0, m1), fminf(m2, m3));
            atomicMin(&g_fmin[pair * NPTS + f], enc_f(mn));
        }
    }

    // Per-pair ticket (all CSPLIT blocks participate, even if nf==0).
    __syncthreads();
    if (tid == 0) {
        __threadfence();
        sticket = atomicAdd(&g_pdone[pair], 1u);
    }
    __syncthreads();
    if (sticket != CSPLIT - 1) return;

    // Last block of this pair: fold its flagged mins.
    float s = 0.0f;
    for (int f = tid; f < nf; f += THREADS)
        s += dec_f(g_fmin[pair * NPTS + f]) + qp[g_fidx[pair * NPTS + f]].w;
#pragma unroll
    for (int o = 16; o > 0; o >>= 1) s += __shfl_down_sync(0xffffffffu, s, o);
    if ((tid & 31) == 0) red[tid >> 5] = s;
    __syncthreads();
    if (tid < THREADS / 32) {
        s = red[tid];
#pragma unroll
        for (int o = (THREADS / 64); o > 0; o >>= 1)
            s += __shfl_down_sync(0xffu, s, o);
    }
    if (tid == 0) {
        if (s != 0.0f) atomicAdd(&g_acc[dir], (double)s);
        __threadfence();
        sticket = atomicAdd(&g_done, 1u);
    }
    __syncthreads();
    if (sticket == 2 * BATCH - 1 && tid < 2) {
        // Final pair folded: all g_acc contributions visible.
        out[tid] = (float)(g_acc[tid] / (double)(BATCH * NPTS));
    }
}

extern "C" void kernel_launch(void* const* d_in, const int* in_sizes, int n_in,
                              void* d_out, int out_size)
{
    const float* xyz1 = (const float*)d_in[0];
    const float* xyz2 = (const float*)d_in[1];
    float* out = (float*)d_out;

    bin_kernel<<<dim3(BATCH, 2), 1024>>>(xyz1, xyz2);
    phase1_kernel<<<dim3(GRIDX, BATCH, 2), THREADS>>>();        // 256 blocks
    phase2_kernel<<<dim3(CSPLIT, 2 * BATCH), THREADS>>>(out);   // 256 blocks
}

// round 17
// speedup vs baseline: 1.3823x; 1.0580x over previous
#include <cuda_runtime.h>

#define BATCH   16
#define NPTS    4096
#define NB      128
#define THREADS 256
#define PPT     2
#define QPB     (THREADS * PPT)      // 512 queries per phase1 block
#define GRIDX   (NPTS / QPB)         // 8 -> phase1 grid (8,16,2) = 256 blocks
#define TILECAP 1024                 // smem candidate tile (16KB)
#define MARGIN  2                    // phase-1 window margin (buckets)
#define CSPLIT  8                    // phase-2 candidate splits
#define CSEG    (NPTS / CSPLIT)      // 512
#define XMIN_F  (-6.0f)
#define XMAX_F  (6.0f)
#define WBUCK   ((XMAX_F - XMIN_F) / (float)NB)
#define BSCALE  ((float)NB / (XMAX_F - XMIN_F))

__device__ double       g_acc[2];
__device__ float4       g_pts[2 * BATCH * NPTS];     // binned (x,y,z,||p||^2)
__device__ int          g_off[2 * BATCH * (NB + 1)];
__device__ int          g_fcnt[2 * BATCH];           // flagged count per pair
__device__ int          g_fidx[2 * BATCH * NPTS];    // flagged query indices
__device__ unsigned int g_fmin[2 * BATCH * NPTS];    // flagged partial mins (enc)
__device__ unsigned int g_pdone[2 * BATCH];          // per-pair phase2 tickets
__device__ unsigned int g_done;                      // global fold ticket

__device__ __forceinline__ unsigned int enc_f(float f) {
    unsigned int u = __float_as_uint(f);
    return (u & 0x80000000u) ? ~u : (u | 0x80000000u);
}
__device__ __forceinline__ float dec_f(unsigned int k) {
    unsigned int u = (k & 0x80000000u) ? (k & 0x7FFFFFFFu) : ~k;
    return __uint_as_float(u);
}

// One block per (batch, set): histogram -> parallel prefix -> scatter.
// Vectorized: each thread handles 4 points via 3 float4 loads.
__global__ __launch_bounds__(1024) void bin_kernel(
    const float* __restrict__ xyz1, const float* __restrict__ xyz2)
{
    const int b = blockIdx.x, set = blockIdx.y;
    if (b == 0 && set == 0) {
        if (threadIdx.x < 2)  g_acc[threadIdx.x] = 0.0;
        if (threadIdx.x < 2 * BATCH) { g_fcnt[threadIdx.x] = 0; g_pdone[threadIdx.x] = 0u; }
        if (threadIdx.x == 0) g_done = 0u;
    }

    const float4* __restrict__ src4 = (const float4*)
        (((set == 0) ? xyz1 : xyz2) + (size_t)b * NPTS * 3);
    __shared__ int cnt[NB];
    __shared__ int cur[NB + 1];
    __shared__ int wsum[NB / 32];
    const int tid = threadIdx.x;

    // Each thread owns 4 points (NPTS/4 = 1024 groups, 1024 threads).
    float4 v0 = src4[tid * 3 + 0];   // p0.x p0.y p0.z p1.x
    float4 v1 = src4[tid * 3 + 1];   // p1.y p1.z p2.x p2.y
    float4 v2 = src4[tid * 3 + 2];   // p2.z p3.x p3.y p3.z
    float px[4] = {v0.x, v0.w, v1.z, v2.y};
    float py[4] = {v0.y, v1.x, v1.w, v2.z};
    float pz[4] = {v0.z, v1.y, v2.x, v2.w};
    int   bk[4];
#pragma unroll
    for (int p = 0; p < 4; p++)
        bk[p] = min(max((int)((px[p] - XMIN_F) * BSCALE), 0), NB - 1);

    for (int k = tid; k < NB; k += 1024) cnt[k] = 0;
    __syncthreads();
#pragma unroll
    for (int p = 0; p < 4; p++) atomicAdd(&cnt[bk[p]], 1);
    __syncthreads();
    int v = 0, s = 0;
    if (tid < NB) {
        v = cnt[tid]; s = v;
#pragma unroll
        for (int o = 1; o < 32; o <<= 1) {
            int n = __shfl_up_sync(0xffffffffu, s, o);
            if ((tid & 31) >= o) s += n;
        }
        if ((tid & 31) == 31) wsum[tid >> 5] = s;
    }
    __syncthreads();
    if (tid < NB) {
        int add = 0;
#pragma unroll
        for (int k = 0; k < NB / 32; k++) if (k < (tid >> 5)) add += wsum[k];
        cur[tid] = s - v + add;
        if (tid == NB - 1) cur[NB] = s + add;
    }
    __syncthreads();
    int* off = g_off + (set * BATCH + b) * (NB + 1);
    for (int k = tid; k <= NB; k += 1024) off[k] = cur[k];
    float4* dst = g_pts + (set * BATCH + b) * NPTS;
#pragma unroll
    for (int p = 0; p < 4; p++) {
        int pos = atomicAdd(&cur[bk[p]], 1);
        dst[pos] = make_float4(px[p], py[p], pz[p],
                               px[p] * px[p] + py[p] * py[p] + pz[p] * pz[p]);
    }
}

// Phase 1: fixed block-window dense scan + per-query certification (PPT=2).
__global__ __launch_bounds__(THREADS) void phase1_kernel()
{
    const int dir  = blockIdx.z;
    const int b    = blockIdx.y;
    const int pair = dir * BATCH + b;
    const int tid  = threadIdx.x;
    const int lane = tid & 31;

    __shared__ float4 tile[TILECAP];
    __shared__ int    soff[NB + 1];
    __shared__ int    sj[2];
    __shared__ float  red[THREADS / 32];

    const float4* __restrict__ qp = g_pts + (dir * BATCH + b) * NPTS;
    const float4* __restrict__ cp = g_pts + ((1 - dir) * BATCH + b) * NPTS;
    const int*    __restrict__ go = g_off + ((1 - dir) * BATCH + b) * (NB + 1);

    for (int k = tid; k <= NB; k += THREADS) soff[k] = go[k];

    const int q0 = blockIdx.x * QPB;
    float rx[PPT], qx[PPT], qy[PPT], qz[PPT], qs[PPT], mn[PPT];
#pragma unroll
    for (int p = 0; p < PPT; p++) {
        float4 v = qp[q0 + tid + p * THREADS];
        rx[p] = v.x;
        qx[p] = -2.0f * v.x; qy[p] = -2.0f * v.y; qz[p] = -2.0f * v.z;
        qs[p] = v.w;
        mn[p] = 3.4e38f;
    }
    if (tid == 0)
        sj[0] = min(max((int)((qp[q0].x - XMIN_F) * BSCALE), 0), NB - 1);
    if (tid == THREADS - 1)
        sj[1] = min(max((int)((qp[q0 + QPB - 1].x - XMIN_F) * BSCALE), 0), NB - 1);
    __syncthreads();
    const int wl = max(sj[0] - MARGIN, 0);
    const int wh = min(sj[1] + MARGIN, NB - 1);
    const int m0 = soff[wl], m1 = soff[wh + 1];

    // Dense smem scan over the window.
    for (int base = m0; base < m1; base += TILECAP) {
        int cnt = min(TILECAP, m1 - base);
        __syncthreads();
        for (int i = tid; i < cnt; i += THREADS) tile[i] = cp[base + i];
        __syncthreads();
#pragma unroll 4
        for (int i = 0; i < cnt; i++) {
            float4 cv = tile[i];
#pragma unroll
            for (int p = 0; p < PPT; p++) {
                float t = fmaf(qx[p], cv.x,
                          fmaf(qy[p], cv.y,
                          fmaf(qz[p], cv.z, cv.w)));
                mn[p] = fminf(mn[p], t);
            }
        }
    }

    // Per-query certification; certified sum here, rest compacted.
    const float el = XMIN_F + wl * WBUCK;
    const float er = XMIN_F + (wh + 1) * WBUCK;
    float s = 0.0f;
#pragma unroll
    for (int p = 0; p < PPT; p++) {
        float d = mn[p] + qs[p];
        bool cl = (wl == 0)      || ((rx[p] - el) * (rx[p] - el) >= d);
        bool cr = (wh == NB - 1) || ((er - rx[p]) * (er - rx[p]) >= d);
        bool cert = cl && cr;
        if (cert) s += d;
        unsigned bal = __ballot_sync(0xffffffffu, !cert);
        if (bal) {
            int leader = __ffs(bal) - 1;
            unsigned basepos = 0;
            if (lane == leader)
                basepos = (unsigned)atomicAdd(&g_fcnt[pair], __popc(bal));
            basepos = __shfl_sync(0xffffffffu, basepos, leader);
            if (!cert) {
                int rank = __popc(bal & ((1u << lane) - 1u));
                int slot = pair * NPTS + (int)basepos + rank;
                g_fidx[slot] = q0 + tid + p * THREADS;
                g_fmin[slot] = 0xFFFFFFFFu;
            }
        }
    }

#pragma unroll
    for (int o = 16; o > 0; o >>= 1) s += __shfl_down_sync(0xffffffffu, s, o);
    if (lane == 0) red[tid >> 5] = s;
    __syncthreads();
    if (tid < THREADS / 32) {
        s = red[tid];
#pragma unroll
        for (int o = (THREADS / 64); o > 0; o >>= 1)
            s += __shfl_down_sync(0xffu, s, o);
        if (tid == 0) atomicAdd(&g_acc[dir], (double)s);
    }
}

// Phase 2: brute-force flagged queries over candidate segments; the last
// block per pair folds that pair; the last folded pair writes the output.
__global__ __launch_bounds__(THREADS) void phase2_kernel(float* out)
{
    const int pair = blockIdx.y;
    const int dir  = pair >> 4;
    const int b    = pair & (BATCH - 1);
    const int tid  = threadIdx.x;
    const int nf   = g_fcnt[pair];

    __shared__ float4       tile[CSEG];
    __shared__ float        red[THREADS / 32];
    __shared__ unsigned int sticket;
    const float4* __restrict__ qp = g_pts + (dir * BATCH + b) * NPTS;
    const float4* __restrict__ cp = g_pts + ((1 - dir) * BATCH + b) * NPTS;

    if (nf > 0) {
        const int seg = blockIdx.x * CSEG;
        for (int i = tid; i < CSEG; i += THREADS) tile[i] = cp[seg + i];
        __syncthreads();

        for (int f = tid; f < nf; f += THREADS) {
            int n = g_fidx[pair * NPTS + f];
            float4 qv = qp[n];
            float qx = -2.0f * qv.x, qy = -2.0f * qv.y, qz = -2.0f * qv.z;
            float m0 = 3.4e38f, m1 = 3.4e38f, m2 = 3.4e38f, m3 = 3.4e38f;
#pragma unroll 4
            for (int i = 0; i < CSEG; i += 4) {
                float4 c0 = tile[i],     c1 = tile[i + 1];
                float4 c2 = tile[i + 2], c3 = tile[i + 3];
                m0 = fminf(m0, fmaf(qx, c0.x, fmaf(qy, c0.y, fmaf(qz, c0.z, c0.w))));
                m1 = fminf(m1, fmaf(qx, c1.x, fmaf(qy, c1.y, fmaf(qz, c1.z, c1.w))));
                m2 = fminf(m2, fmaf(qx, c2.x, fmaf(qy, c2.y, fmaf(qz, c2.z, c2.w))));
                m3 = fminf(m3, fmaf(qx, c3.x, fmaf(qy, c3.y, fmaf(qz, c3.z, c3.w))));
            }
            float mn = fminf(fminf(m0, m1), fminf(m2, m3));
            atomicMin(&g_fmin[pair * NPTS + f], enc_f(mn));
        }
    }

    // Per-pair ticket (all CSPLIT blocks participate, even if nf==0).
    __syncthreads();
    if (tid == 0) {
        __threadfence();
        sticket = atomicAdd(&g_pdone[pair], 1u);
    }
    __syncthreads();
    if (sticket != CSPLIT - 1) return;

    // Last block of this pair: fold its flagged mins.
    float s = 0.0f;
    for (int f = tid; f < nf; f += THREADS)
        s += dec_f(g_fmin[pair * NPTS + f]) + qp[g_fidx[pair * NPTS + f]].w;
#pragma unroll
    for (int o = 16; o > 0; o >>= 1) s += __shfl_down_sync(0xffffffffu, s, o);
    if ((tid & 31) == 0) red[tid >> 5] = s;
    __syncthreads();
    if (tid < THREADS / 32) {
        s = red[tid];
#pragma unroll
        for (int o = (THREADS / 64); o > 0; o >>= 1)
            s += __shfl_down_sync(0xffu, s, o);
    }
    if (tid == 0) {
        if (s != 0.0f) atomicAdd(&g_acc[dir], (double)s);
        __threadfence();
        sticket = atomicAdd(&g_done, 1u);
    }
    __syncthreads();
    if (sticket == 2 * BATCH - 1 && tid < 2) {
        // Final pair folded: all g_acc contributions visible.
        out[tid] = (float)(g_acc[tid] / (double)(BATCH * NPTS));
    }
}

extern "C" void kernel_launch(void* const* d_in, const int* in_sizes, int n_in,
                              void* d_out, int out_size)
{
    const float* xyz1 = (const float*)d_in[0];
    const float* xyz2 = (const float*)d_in[1];
    float* out = (float*)d_out;

    bin_kernel<<<dim3(BATCH, 2), 1024>>>(xyz1, xyz2);
    phase1_kernel<<<dim3(GRIDX, BATCH, 2), THREADS>>>();        // 256 blocks
    phase2_kernel<<<dim3(CSPLIT, 2 * BATCH), THREADS>>>(out);   // 256 blocks
}